// round 15
// baseline (speedup 1.0000x reference)
#include <cuda_runtime.h>
#include <cuda_bf16.h>
#include <cstdint>
#include <math.h>

#define Nn 4096
#define LRALPHA 0.2f
#define ONES2 0x3F803F80u

__device__ unsigned g_adjbits[128 * Nn];
__device__ __nv_bfloat16 g_WhB[4 * 64 * Nn];   // [g][f][node]
__device__ __nv_bfloat16 g_Wh2B[64 * Nn];
__device__ float4 g_rowdat[4 * Nn];            // (s1, e^s1, e^{.2 s1}, _)
__device__ float4 g_coldat[4 * Nn];
__device__ float  g_part[16 * Nn * 64];
__device__ float  g_den[16 * Nn];
__device__ float  g_xres[Nn * 64];
__device__ int    g_ctr[2];

__device__ __forceinline__ uint32_t smem_u32(const void* p) {
    uint32_t a;
    asm("{ .reg .u64 t; cvta.to.shared.u64 t, %1; cvt.u32.u64 %0, t; }" : "=r"(a) : "l"(p));
    return a;
}
__device__ __forceinline__ float eluf(float v) { return v > 0.f ? v : expm1f(v); }
__device__ __forceinline__ float slctf(float a, float b, float c) {
    float d; asm("slct.f32.f32 %0,%1,%2,%3;" : "=f"(d) : "f"(a), "f"(b), "f"(c)); return d;
}
__device__ __forceinline__ float slcti(float a, float b, int c) {
    float d; asm("slct.f32.s32 %0,%1,%2,%3;" : "=f"(d) : "f"(a), "f"(b), "r"(c)); return d;
}

#define CP16(d, s) asm volatile("cp.async.ca.shared.global [%0],[%1],16;" :: "r"(d), "l"(s))
#define CP4(d, s)  asm volatile("cp.async.ca.shared.global [%0],[%1],4;"  :: "r"(d), "l"(s))
#define CPCOMMIT() asm volatile("cp.async.commit_group;")
#define CPWAIT1()  asm volatile("cp.async.wait_group 1;" ::: "memory")

__device__ __forceinline__ void mma16(float* c, uint32_t a0, uint32_t a1, uint32_t a2, uint32_t a3,
                                      uint32_t b0, uint32_t b1) {
    asm("mma.sync.aligned.m16n8k16.row.col.f32.bf16.bf16.f32 "
        "{%0,%1,%2,%3},{%4,%5,%6,%7},{%8,%9},{%0,%1,%2,%3};"
        : "+f"(c[0]), "+f"(c[1]), "+f"(c[2]), "+f"(c[3])
        : "r"(a0), "r"(a1), "r"(a2), "r"(a3), "r"(b0), "r"(b1));
}
#define LDSM4(R0,R1,R2,R3,ADDR) \
    asm volatile("ldmatrix.sync.aligned.m8n8.x4.shared.b16 {%0,%1,%2,%3},[%4];" \
        : "=r"(R0),"=r"(R1),"=r"(R2),"=r"(R3) : "r"(ADDR))

__device__ __forceinline__ uint32_t packbf(float hi, float lo) {
    uint32_t d; asm("cvt.rn.bf16x2.f32 %0, %1, %2;" : "=r"(d) : "f"(hi), "f"(lo));
    return d;
}

__global__ void pack_adj(const int* __restrict__ adj) {
    if (blockIdx.x == 0 && threadIdx.x == 0) { g_ctr[0] = 0; g_ctr[1] = 0; }
    int idx = blockIdx.x * 256 + threadIdx.x;
    int i = idx >> 12, j = idx & 4095;
    unsigned w = __ballot_sync(0xFFFFFFFFu, adj[idx] > 0);
    if ((j & 31) == 0) g_adjbits[(j >> 5) * Nn + i] = w;
}

// Unified GEMM: A-term = [A row] + [combKS: elu(sum_s part / sum_s den)]
// bT: write C^T bf16 (ld Nn). aV: fused attention-score epilogue.
__global__ __launch_bounds__(256)
void gemm64(const float* __restrict__ A,
            const float* __restrict__ PA, const float* __restrict__ PD, int combKS,
            const float* __restrict__ B, const float* __restrict__ bias,
            float* __restrict__ C, int K, int transB, int doElu,
            __nv_bfloat16* __restrict__ bT,
            const float* __restrict__ aV, float4* __restrict__ rowdat, float4* __restrict__ coldat,
            long Bg, long Tg, long Ag)
{
    __shared__ __align__(16) float As[16][68];
    __shared__ __align__(16) float Bs[16][68];
    int gy = blockIdx.y;
    B += (long)gy * Bg;
    if (bT) bT += (long)gy * Tg;
    if (aV) { aV += (long)gy * Ag; rowdat += (long)gy * Nn; coldat += (long)gy * Nn; }
    int tid = threadIdx.x, ibase = blockIdx.x * 64;
    int r0 = (tid >> 4) << 2, c0 = (tid & 15) << 2;
    int ai = tid >> 2, akq = tid & 3;
    float acc[4][4] = {};
    for (int k0 = 0; k0 < K; k0 += 16) {
        __syncthreads();
        int kk = k0 + akq * 4;
        float4 v = make_float4(0.f, 0.f, 0.f, 0.f);
        if (A) v = *(const float4*)&A[(size_t)(ibase + ai) * K + kk];
        if (combKS) {
            int g = kk >> 6, f = kk & 63, row = ibase + ai;
            float4 s = make_float4(0.f, 0.f, 0.f, 0.f); float d = 0.f;
            for (int ss = 0; ss < combKS; ++ss) {
                size_t pb = (size_t)(g * combKS + ss) * Nn + row;
                float4 u = *(const float4*)&PA[pb * 64 + f];
                s.x += u.x; s.y += u.y; s.z += u.z; s.w += u.w;
                d += PD[pb];
            }
            float di = 1.f / d;
            v.x += eluf(s.x * di); v.y += eluf(s.y * di);
            v.z += eluf(s.z * di); v.w += eluf(s.w * di);
        }
        As[akq*4+0][ai] = v.x; As[akq*4+1][ai] = v.y; As[akq*4+2][ai] = v.z; As[akq*4+3][ai] = v.w;
        if (!transB) {
            int bk = tid >> 4, bf = (tid & 15) << 2;
            *(float4*)&Bs[bk][bf] = *(const float4*)&B[(size_t)(k0 + bk) * 64 + bf];
        } else {
            int bf = tid >> 2, bkq = tid & 3;
            float4 u = *(const float4*)&B[(size_t)bf * K + k0 + bkq * 4];
            Bs[bkq*4+0][bf] = u.x; Bs[bkq*4+1][bf] = u.y; Bs[bkq*4+2][bf] = u.z; Bs[bkq*4+3][bf] = u.w;
        }
        __syncthreads();
        #pragma unroll
        for (int k = 0; k < 16; ++k) {
            float4 a4 = *(const float4*)&As[k][r0];
            float4 b4 = *(const float4*)&Bs[k][c0];
            acc[0][0]+=a4.x*b4.x; acc[0][1]+=a4.x*b4.y; acc[0][2]+=a4.x*b4.z; acc[0][3]+=a4.x*b4.w;
            acc[1][0]+=a4.y*b4.x; acc[1][1]+=a4.y*b4.y; acc[1][2]+=a4.y*b4.z; acc[1][3]+=a4.y*b4.w;
            acc[2][0]+=a4.z*b4.x; acc[2][1]+=a4.z*b4.y; acc[2][2]+=a4.z*b4.z; acc[2][3]+=a4.z*b4.w;
            acc[3][0]+=a4.w*b4.x; acc[3][1]+=a4.w*b4.y; acc[3][2]+=a4.w*b4.z; acc[3][3]+=a4.w*b4.w;
        }
    }
    if (C) {
        float b0 = bias?bias[c0]:0.f, b1 = bias?bias[c0+1]:0.f, b2 = bias?bias[c0+2]:0.f, b3 = bias?bias[c0+3]:0.f;
        #pragma unroll
        for (int r = 0; r < 4; ++r) {
            float4 o = make_float4(acc[r][0]+b0, acc[r][1]+b1, acc[r][2]+b2, acc[r][3]+b3);
            if (doElu) { o.x=eluf(o.x); o.y=eluf(o.y); o.z=eluf(o.z); o.w=eluf(o.w); }
            *(float4*)&C[(size_t)(ibase + r0 + r) * 64 + c0] = o;
        }
    }
    if (bT) {
        #pragma unroll
        for (int c = 0; c < 4; ++c) {
            ushort4 h;
            h.x = __bfloat16_as_ushort(__float2bfloat16_rn(acc[0][c]));
            h.y = __bfloat16_as_ushort(__float2bfloat16_rn(acc[1][c]));
            h.z = __bfloat16_as_ushort(__float2bfloat16_rn(acc[2][c]));
            h.w = __bfloat16_as_ushort(__float2bfloat16_rn(acc[3][c]));
            *(ushort4*)&bT[(size_t)(c0 + c) * Nn + ibase + r0] = h;
        }
    }
    if (aV) {
        float s1[4], s2[4];
        #pragma unroll
        for (int r = 0; r < 4; ++r) {
            s1[r] = acc[r][0]*aV[c0] + acc[r][1]*aV[c0+1] + acc[r][2]*aV[c0+2] + acc[r][3]*aV[c0+3];
            s2[r] = acc[r][0]*aV[64+c0] + acc[r][1]*aV[64+c0+1] + acc[r][2]*aV[64+c0+2] + acc[r][3]*aV[64+c0+3];
            #pragma unroll
            for (int off = 1; off < 16; off <<= 1) {
                s1[r] += __shfl_xor_sync(0xFFFFFFFFu, s1[r], off, 16);
                s2[r] += __shfl_xor_sync(0xFFFFFFFFu, s2[r], off, 16);
            }
        }
        if ((tid & 15) == 0) {
            #pragma unroll
            for (int r = 0; r < 4; ++r) {
                int row = ibase + r0 + r;
                rowdat[row] = make_float4(s1[r], expf(s1[r]), expf(LRALPHA*s1[r]), 0.f);
                coldat[row] = make_float4(s2[r], expf(s2[r]), expf(LRALPHA*s2[r]), 0.f);
            }
        }
    }
}

// masked-softmax aggregation: bf16 m16n8k16 mma.sync, A built in registers.
// 128 threads / 4 warps; each warp owns 32 rows (2 m16 tiles). TJ=128 per stage.
// B fragments via ldmatrix.x4 (stride 136 bf16 -> conflict-free).
__global__ __launch_bounds__(128, 3)
void gat_attn_mma(const __nv_bfloat16* __restrict__ WhB, const float4* __restrict__ rowdat,
                  const float4* __restrict__ coldat, float* __restrict__ part,
                  float* __restrict__ den, int G, int ksplit, int layer)
{
    __shared__ __align__(16) __nv_bfloat16 Bsm[2][64 * 136];
    __shared__ unsigned bitsS[2][4][128];
    __shared__ __align__(16) float4 cdsS[2][128];
    __shared__ int itemS;

    int tid = threadIdx.x, w = tid >> 5, lane = tid & 31;
    int la = lane & 3, lp = lane >> 2;
    uint32_t bsB = smem_u32(&Bsm[0][0]);
    uint32_t btB = smem_u32(&bitsS[0][0][0]);
    uint32_t cdB = smem_u32(&cdsS[0][0]);
    // ldmatrix lane address: row = (lane&7) | ((lane>>4)<<3), k-offset = ((lane>>3)&1)*8
    int ldrow = (lane & 7) | ((lane >> 4) << 3);
    int ldoff = (ldrow * 136 + (((lane >> 3) & 1) << 3)) * 2;

    int jchunk = Nn / ksplit, ntiles = jchunk / 128;
    int nItems = 32 * G * ksplit;

    while (true) {
        if (tid == 0) itemS = atomicAdd(&g_ctr[layer], 1);
        __syncthreads();
        int item = itemS;
        if (item >= nItems) break;
        int ib = item & 31, rest = item >> 5;
        int g = rest % G, ks = rest / G;
        int ibase = ib * 128, jbase0 = ks * jchunk;
        int gN = g * Nn;
        const __nv_bfloat16* WhBg = WhB + (size_t)g * 64 * Nn;

        float4 rdv[4];
        #pragma unroll
        for (int h = 0; h < 4; ++h) rdv[h] = rowdat[gN + ibase + w*32 + 8*h + lp];
        float cA[2][8][4];
        float cD[2][4];
        #pragma unroll
        for (int m = 0; m < 2; ++m) {
            #pragma unroll
            for (int n = 0; n < 8; ++n) { cA[m][n][0]=0.f; cA[m][n][1]=0.f; cA[m][n][2]=0.f; cA[m][n][3]=0.f; }
            cD[m][0]=0.f; cD[m][1]=0.f; cD[m][2]=0.f; cD[m][3]=0.f;
        }

        auto stage = [&](int jbase, int buf) {
            #pragma unroll
            for (int r = 0; r < 8; ++r) {
                int e = tid + 128 * r;
                int f = e >> 4, ch = e & 15;
                CP16(bsB + (uint32_t)(buf * 17408 + (f * 136 + ch * 8) * 2),
                     WhBg + (size_t)f * Nn + jbase + ch * 8);
            }
            #pragma unroll
            for (int q = 0; q < 4; ++q)
                CP4(btB + (uint32_t)(((buf*4+q)*128 + tid) * 4),
                    &g_adjbits[((jbase >> 5) + q) * Nn + ibase + tid]);
            CP16(cdB + (uint32_t)((buf*128 + tid) * 16), &coldat[gN + jbase + tid]);
            CPCOMMIT();
        };

        stage(jbase0, 0);
        int buf = 0;
        for (int t = 0; t < ntiles; ++t) {
            if (t + 1 < ntiles) stage(jbase0 + (t + 1) * 128, buf ^ 1);
            else CPCOMMIT();
            CPWAIT1();
            __syncthreads();
            unsigned rbw[4][4];
            #pragma unroll
            for (int q = 0; q < 4; ++q)
                #pragma unroll
                for (int h = 0; h < 4; ++h) rbw[q][h] = bitsS[buf][q][w*32 + 8*h + lp];
            uint32_t bB = bsB + buf * 17408 + ldoff;
            const float4* cds = &cdsS[buf][0];
            #pragma unroll
            for (int ks2 = 0; ks2 < 8; ++ks2) {
                int jk = ks2 * 16;
                int jl = (jk & 31) + 2*la;
                int wsel = ks2 >> 1;
                float4 c0 = cds[jk + 2*la];
                float4 c1 = cds[jk + 2*la + 1];
                float4 c2 = cds[jk + 2*la + 8];
                float4 c3 = cds[jk + 2*la + 9];
                uint32_t Alo[4], Ahi[4];
                #pragma unroll
                for (int h = 0; h < 4; ++h) {
                    unsigned rb = rbw[wsel][h];
                    float rx = rdv[h].x, ry = rdv[h].y, rz = rdv[h].z;
                    float p0 = slctf(ry*c0.y, rz*c0.z, rx + c0.x);
                    float p1 = slctf(ry*c1.y, rz*c1.z, rx + c1.x);
                    float p2 = slctf(ry*c2.y, rz*c2.z, rx + c2.x);
                    float p3 = slctf(ry*c3.y, rz*c3.z, rx + c3.x);
                    float w0 = slcti(0.f, p0, (int)(rb << (31 - jl)));
                    float w1 = slcti(0.f, p1, (int)(rb << (30 - jl)));
                    float w2 = slcti(0.f, p2, (int)(rb << (23 - jl)));
                    float w3 = slcti(0.f, p3, (int)(rb << (22 - jl)));
                    Alo[h] = packbf(w1, w0);
                    Ahi[h] = packbf(w3, w2);
                }
                #pragma unroll
                for (int q = 0; q < 4; ++q) {
                    uint32_t b0, b1, b2, b3;
                    LDSM4(b0, b1, b2, b3, bB + q * 4352 + jk * 2);
                    mma16(cA[0][2*q],   Alo[0], Alo[1], Ahi[0], Ahi[1], b0, b1);
                    mma16(cA[1][2*q],   Alo[2], Alo[3], Ahi[2], Ahi[3], b0, b1);
                    mma16(cA[0][2*q+1], Alo[0], Alo[1], Ahi[0], Ahi[1], b2, b3);
                    mma16(cA[1][2*q+1], Alo[2], Alo[3], Ahi[2], Ahi[3], b2, b3);
                }
                mma16(cD[0], Alo[0], Alo[1], Ahi[0], Ahi[1], ONES2, ONES2);
                mma16(cD[1], Alo[2], Alo[3], Ahi[2], Ahi[3], ONES2, ONES2);
            }
            __syncthreads();
            buf ^= 1;
        }
        int p = g * ksplit + ks;
        if (la == 0) {
            int r = ibase + w*32 + lp;
            den[(size_t)p * Nn + r]      = cD[0][0];
            den[(size_t)p * Nn + r + 8]  = cD[0][2];
            den[(size_t)p * Nn + r + 16] = cD[1][0];
            den[(size_t)p * Nn + r + 24] = cD[1][2];
        }
        #pragma unroll
        for (int m = 0; m < 2; ++m) {
            int r0 = ibase + w*32 + 16*m + lp;
            #pragma unroll
            for (int n = 0; n < 8; ++n) {
                float* d0 = &part[((size_t)p * Nn + r0) * 64 + n*8 + 2*la];
                *(float2*)d0 = make_float2(cA[m][n][0], cA[m][n][1]);
                *(float2*)(d0 + 8 * 64) = make_float2(cA[m][n][2], cA[m][n][3]);
            }
        }
    }
}

extern "C" void kernel_launch(void* const* d_in, const int* in_sizes, int n_in,
                              void* d_out, int out_size)
{
    const float* x        = (const float*)d_in[0];
    const int*   adj      = (const int*)d_in[1];
    const float* w_heads  = (const float*)d_in[2];
    const float* a_heads  = (const float*)d_in[3];
    const float* w_out    = (const float*)d_in[4];
    const float* a_out    = (const float*)d_in[5];
    const float* lin_w    = (const float*)d_in[6];
    const float* lin_b    = (const float*)d_in[7];
    const float* outlin_w = (const float*)d_in[8];
    const float* outlin_b = (const float*)d_in[9];
    float* out = (float*)d_out;

    float *pXres, *pPart, *pDen;
    __nv_bfloat16 *pWhB, *pWh2B;
    float4 *pRow, *pCol;
    cudaGetSymbolAddress((void**)&pWhB,  g_WhB);
    cudaGetSymbolAddress((void**)&pWh2B, g_Wh2B);
    cudaGetSymbolAddress((void**)&pXres, g_xres);
    cudaGetSymbolAddress((void**)&pPart, g_part);
    cudaGetSymbolAddress((void**)&pDen,  g_den);
    cudaGetSymbolAddress((void**)&pRow,  g_rowdat);
    cudaGetSymbolAddress((void**)&pCol,  g_coldat);

    pack_adj<<<(Nn * Nn) / 256, 256>>>(adj);
    // layer-1: Wh per head -> bf16 transposed + fused scores
    gemm64<<<dim3(Nn/64, 4), 256>>>(x, nullptr, nullptr, 0, w_heads, nullptr, nullptr, 128, 0, 0,
                                    pWhB, a_heads, pRow, pCol, 128L*64, 64L*Nn, 128);
    gemm64<<<dim3(Nn/64, 1), 256>>>(x, nullptr, nullptr, 0, lin_w, lin_b, pXres, 128, 1, 0,
                                    nullptr, nullptr, nullptr, nullptr, 0, 0, 0);
    gat_attn_mma<<<444, 128>>>(pWhB, pRow, pCol, pPart, pDen, 4, 2, 0);
    // layer-2 Wh GEMM with fused combine(part,den) as input, + bf16T + scores
    gemm64<<<dim3(Nn/64, 1), 256>>>(nullptr, pPart, pDen, 2, w_out, nullptr, nullptr, 256, 0, 0,
                                    pWh2B, a_out, pRow, pCol, 0, 0, 0);
    gat_attn_mma<<<444, 128>>>(pWh2B, pRow, pCol, pPart, pDen, 1, 8, 1);
    // final: elu((xres + elu(combine)) @ outlin^T + b)
    gemm64<<<dim3(Nn/64, 1), 256>>>(pXres, pPart, pDen, 8, outlin_w, outlin_b, out, 64, 1, 1,
                                    nullptr, nullptr, nullptr, nullptr, 0, 0, 0);
}

// round 17
// speedup vs baseline: 1.5426x; 1.5426x over previous
#include <cuda_runtime.h>
#include <cuda_bf16.h>
#include <cstdint>
#include <math.h>

#define Nn 4096
#define LRALPHA 0.2f
#define ONES2 0x3F803F80u

__device__ unsigned g_adjbits[128 * Nn];
__device__ __nv_bfloat16 g_WhB[4 * 64 * Nn];   // [g][f][node]
__device__ __nv_bfloat16 g_Wh2B[64 * Nn];
__device__ float4 g_rowdat[4 * Nn];            // (s1, e^s1, e^{.2 s1}, _)
__device__ float4 g_coldat[4 * Nn];
__device__ float  g_part[16 * Nn * 64];
__device__ float  g_den[16 * Nn];
__device__ float  g_xres[Nn * 64];
__device__ int    g_ctr[2];

__device__ __forceinline__ uint32_t smem_u32(const void* p) {
    uint32_t a;
    asm("{ .reg .u64 t; cvta.to.shared.u64 t, %1; cvt.u32.u64 %0, t; }" : "=r"(a) : "l"(p));
    return a;
}
__device__ __forceinline__ float eluf(float v) { return v > 0.f ? v : expm1f(v); }
__device__ __forceinline__ float slctf(float a, float b, float c) {
    float d; asm("slct.f32.f32 %0,%1,%2,%3;" : "=f"(d) : "f"(a), "f"(b), "f"(c)); return d;
}
__device__ __forceinline__ float slcti(float a, float b, int c) {
    float d; asm("slct.f32.s32 %0,%1,%2,%3;" : "=f"(d) : "f"(a), "f"(b), "r"(c)); return d;
}

#define CP16(d, s) asm volatile("cp.async.ca.shared.global [%0],[%1],16;" :: "r"(d), "l"(s))
#define CP4(d, s)  asm volatile("cp.async.ca.shared.global [%0],[%1],4;"  :: "r"(d), "l"(s))
#define CPCOMMIT() asm volatile("cp.async.commit_group;")
#define CPWAIT1()  asm volatile("cp.async.wait_group 1;" ::: "memory")

__device__ __forceinline__ void mma16(float* c, uint32_t a0, uint32_t a1, uint32_t a2, uint32_t a3,
                                      uint32_t b0, uint32_t b1) {
    asm("mma.sync.aligned.m16n8k16.row.col.f32.bf16.bf16.f32 "
        "{%0,%1,%2,%3},{%4,%5,%6,%7},{%8,%9},{%0,%1,%2,%3};"
        : "+f"(c[0]), "+f"(c[1]), "+f"(c[2]), "+f"(c[3])
        : "r"(a0), "r"(a1), "r"(a2), "r"(a3), "r"(b0), "r"(b1));
}
__device__ __forceinline__ uint32_t packbf(float hi, float lo) {
    uint32_t d; asm("cvt.rn.bf16x2.f32 %0, %1, %2;" : "=r"(d) : "f"(hi), "f"(lo));
    return d;
}

__global__ void pack_adj(const int* __restrict__ adj) {
    if (blockIdx.x == 0 && threadIdx.x == 0) { g_ctr[0] = 0; g_ctr[1] = 0; }
    int idx = blockIdx.x * 256 + threadIdx.x;
    int i = idx >> 12, j = idx & 4095;
    unsigned w = __ballot_sync(0xFFFFFFFFu, adj[idx] > 0);
    if ((j & 31) == 0) g_adjbits[(j >> 5) * Nn + i] = w;
}

// Unified GEMM: A-term = [A row] + [combKS: elu(sum_s part / sum_s den)]
// bT: write C^T bf16 (ld Nn). aV: fused attention-score epilogue.
__global__ __launch_bounds__(256)
void gemm64(const float* __restrict__ A,
            const float* __restrict__ PA, const float* __restrict__ PD, int combKS,
            const float* __restrict__ B, const float* __restrict__ bias,
            float* __restrict__ C, int K, int transB, int doElu,
            __nv_bfloat16* __restrict__ bT,
            const float* __restrict__ aV, float4* __restrict__ rowdat, float4* __restrict__ coldat,
            long Bg, long Tg, long Ag)
{
    __shared__ __align__(16) float As[16][68];
    __shared__ __align__(16) float Bs[16][68];
    int gy = blockIdx.y;
    B += (long)gy * Bg;
    if (bT) bT += (long)gy * Tg;
    if (aV) { aV += (long)gy * Ag; rowdat += (long)gy * Nn; coldat += (long)gy * Nn; }
    int tid = threadIdx.x, ibase = blockIdx.x * 64;
    int r0 = (tid >> 4) << 2, c0 = (tid & 15) << 2;
    int ai = tid >> 2, akq = tid & 3;
    float acc[4][4] = {};
    for (int k0 = 0; k0 < K; k0 += 16) {
        __syncthreads();
        int kk = k0 + akq * 4;
        float4 v = make_float4(0.f, 0.f, 0.f, 0.f);
        if (A) v = *(const float4*)&A[(size_t)(ibase + ai) * K + kk];
        if (combKS) {
            int g = kk >> 6, f = kk & 63, row = ibase + ai;
            float4 s = make_float4(0.f, 0.f, 0.f, 0.f); float d = 0.f;
            for (int ss = 0; ss < combKS; ++ss) {
                size_t pb = (size_t)(g * combKS + ss) * Nn + row;
                float4 u = *(const float4*)&PA[pb * 64 + f];
                s.x += u.x; s.y += u.y; s.z += u.z; s.w += u.w;
                d += PD[pb];
            }
            float di = 1.f / d;
            v.x += eluf(s.x * di); v.y += eluf(s.y * di);
            v.z += eluf(s.z * di); v.w += eluf(s.w * di);
        }
        As[akq*4+0][ai] = v.x; As[akq*4+1][ai] = v.y; As[akq*4+2][ai] = v.z; As[akq*4+3][ai] = v.w;
        if (!transB) {
            int bk = tid >> 4, bf = (tid & 15) << 2;
            *(float4*)&Bs[bk][bf] = *(const float4*)&B[(size_t)(k0 + bk) * 64 + bf];
        } else {
            int bf = tid >> 2, bkq = tid & 3;
            float4 u = *(const float4*)&B[(size_t)bf * K + k0 + bkq * 4];
            Bs[bkq*4+0][bf] = u.x; Bs[bkq*4+1][bf] = u.y; Bs[bkq*4+2][bf] = u.z; Bs[bkq*4+3][bf] = u.w;
        }
        __syncthreads();
        #pragma unroll
        for (int k = 0; k < 16; ++k) {
            float4 a4 = *(const float4*)&As[k][r0];
            float4 b4 = *(const float4*)&Bs[k][c0];
            acc[0][0]+=a4.x*b4.x; acc[0][1]+=a4.x*b4.y; acc[0][2]+=a4.x*b4.z; acc[0][3]+=a4.x*b4.w;
            acc[1][0]+=a4.y*b4.x; acc[1][1]+=a4.y*b4.y; acc[1][2]+=a4.y*b4.z; acc[1][3]+=a4.y*b4.w;
            acc[2][0]+=a4.z*b4.x; acc[2][1]+=a4.z*b4.y; acc[2][2]+=a4.z*b4.z; acc[2][3]+=a4.z*b4.w;
            acc[3][0]+=a4.w*b4.x; acc[3][1]+=a4.w*b4.y; acc[3][2]+=a4.w*b4.z; acc[3][3]+=a4.w*b4.w;
        }
    }
    if (C) {
        float b0 = bias?bias[c0]:0.f, b1 = bias?bias[c0+1]:0.f, b2 = bias?bias[c0+2]:0.f, b3 = bias?bias[c0+3]:0.f;
        #pragma unroll
        for (int r = 0; r < 4; ++r) {
            float4 o = make_float4(acc[r][0]+b0, acc[r][1]+b1, acc[r][2]+b2, acc[r][3]+b3);
            if (doElu) { o.x=eluf(o.x); o.y=eluf(o.y); o.z=eluf(o.z); o.w=eluf(o.w); }
            *(float4*)&C[(size_t)(ibase + r0 + r) * 64 + c0] = o;
        }
    }
    if (bT) {
        #pragma unroll
        for (int c = 0; c < 4; ++c) {
            ushort4 h;
            h.x = __bfloat16_as_ushort(__float2bfloat16_rn(acc[0][c]));
            h.y = __bfloat16_as_ushort(__float2bfloat16_rn(acc[1][c]));
            h.z = __bfloat16_as_ushort(__float2bfloat16_rn(acc[2][c]));
            h.w = __bfloat16_as_ushort(__float2bfloat16_rn(acc[3][c]));
            *(ushort4*)&bT[(size_t)(c0 + c) * Nn + ibase + r0] = h;
        }
    }
    if (aV) {
        float s1[4], s2[4];
        #pragma unroll
        for (int r = 0; r < 4; ++r) {
            s1[r] = acc[r][0]*aV[c0] + acc[r][1]*aV[c0+1] + acc[r][2]*aV[c0+2] + acc[r][3]*aV[c0+3];
            s2[r] = acc[r][0]*aV[64+c0] + acc[r][1]*aV[64+c0+1] + acc[r][2]*aV[64+c0+2] + acc[r][3]*aV[64+c0+3];
            #pragma unroll
            for (int off = 1; off < 16; off <<= 1) {
                s1[r] += __shfl_xor_sync(0xFFFFFFFFu, s1[r], off, 16);
                s2[r] += __shfl_xor_sync(0xFFFFFFFFu, s2[r], off, 16);
            }
        }
        if ((tid & 15) == 0) {
            #pragma unroll
            for (int r = 0; r < 4; ++r) {
                int row = ibase + r0 + r;
                rowdat[row] = make_float4(s1[r], expf(s1[r]), expf(LRALPHA*s1[r]), 0.f);
                coldat[row] = make_float4(s2[r], expf(s2[r]), expf(LRALPHA*s2[r]), 0.f);
            }
        }
    }
}

// masked-softmax aggregation: bf16 m16n8k16 mma.sync, A built in registers,
// denominator via all-ones B fragment MMA. TJ=64 per stage. (R11 proven config)
__global__ __launch_bounds__(128)
void gat_attn_mma(const __nv_bfloat16* __restrict__ WhB, const float4* __restrict__ rowdat,
                  const float4* __restrict__ coldat, float* __restrict__ part,
                  float* __restrict__ den, int G, int ksplit, int layer)
{
    __shared__ __align__(16) __nv_bfloat16 Bsm[2][64 * 72];
    __shared__ unsigned bitsS[2][2][128];
    __shared__ __align__(16) float4 cdsS[2][64];
    __shared__ int itemS;

    int tid = threadIdx.x, w = tid >> 5, lane = tid & 31;
    int la = lane & 3, lp = lane >> 2;
    uint32_t bsB = smem_u32(&Bsm[0][0]);
    uint32_t btB = smem_u32(&bitsS[0][0][0]);
    uint32_t cdB = smem_u32(&cdsS[0][0]);

    int jchunk = Nn / ksplit, ntiles = jchunk / 64;
    int nItems = 32 * G * ksplit;

    while (true) {
        if (tid == 0) itemS = atomicAdd(&g_ctr[layer], 1);
        __syncthreads();
        int item = itemS;
        if (item >= nItems) break;
        int ib = item & 31, rest = item >> 5;
        int g = rest % G, ks = rest / G;
        int ibase = ib * 128, jbase0 = ks * jchunk;
        int gN = g * Nn;
        const __nv_bfloat16* WhBg = WhB + (size_t)g * 64 * Nn;

        float4 rdv[4];
        #pragma unroll
        for (int h = 0; h < 4; ++h) rdv[h] = rowdat[gN + ibase + w*32 + 8*h + lp];
        float cA[2][8][4];
        float cD[2][4];
        #pragma unroll
        for (int m = 0; m < 2; ++m) {
            #pragma unroll
            for (int n = 0; n < 8; ++n) { cA[m][n][0]=0.f; cA[m][n][1]=0.f; cA[m][n][2]=0.f; cA[m][n][3]=0.f; }
            cD[m][0]=0.f; cD[m][1]=0.f; cD[m][2]=0.f; cD[m][3]=0.f;
        }

        auto stage = [&](int jbase, int buf) {
            #pragma unroll
            for (int r = 0; r < 4; ++r) {
                int e = tid + 128 * r;
                int f = e >> 3, ch = e & 7;
                CP16(bsB + (uint32_t)(buf * 9216 + f * 144 + ch * 16),
                     WhBg + (size_t)f * Nn + jbase + ch * 8);
            }
            CP4(btB + (uint32_t)((buf*2+0)*512 + tid*4), &g_adjbits[((jbase>>5)+0)*Nn + ibase + tid]);
            CP4(btB + (uint32_t)((buf*2+1)*512 + tid*4), &g_adjbits[((jbase>>5)+1)*Nn + ibase + tid]);
            if (tid < 64) CP16(cdB + (uint32_t)(buf*64 + tid)*16, &coldat[gN + jbase + tid]);
            CPCOMMIT();
        };

        stage(jbase0, 0);
        int buf = 0;
        for (int t = 0; t < ntiles; ++t) {
            if (t + 1 < ntiles) stage(jbase0 + (t + 1) * 64, buf ^ 1);
            else CPCOMMIT();
            CPWAIT1();
            __syncthreads();
            unsigned rbw[2][4];
            #pragma unroll
            for (int h = 0; h < 4; ++h) {
                rbw[0][h] = bitsS[buf][0][w*32 + 8*h + lp];
                rbw[1][h] = bitsS[buf][1][w*32 + 8*h + lp];
            }
            const __nv_bfloat16* bbase = &Bsm[buf][0];
            #pragma unroll
            for (int ks2 = 0; ks2 < 4; ++ks2) {
                int jk = ks2 * 16;
                int jl = (jk & 31) + 2*la;
                int wsel = ks2 >> 1;
                float4 c0 = cdsS[buf][jk + 2*la];
                float4 c1 = cdsS[buf][jk + 2*la + 1];
                float4 c2 = cdsS[buf][jk + 2*la + 8];
                float4 c3 = cdsS[buf][jk + 2*la + 9];
                uint32_t Alo[4], Ahi[4];
                #pragma unroll
                for (int h = 0; h < 4; ++h) {
                    unsigned rb = rbw[wsel][h];
                    float rx = rdv[h].x, ry = rdv[h].y, rz = rdv[h].z;
                    float p0 = slctf(ry*c0.y, rz*c0.z, rx + c0.x);
                    float p1 = slctf(ry*c1.y, rz*c1.z, rx + c1.x);
                    float p2 = slctf(ry*c2.y, rz*c2.z, rx + c2.x);
                    float p3 = slctf(ry*c3.y, rz*c3.z, rx + c3.x);
                    float w0 = slcti(0.f, p0, (int)(rb << (31 - jl)));
                    float w1 = slcti(0.f, p1, (int)(rb << (30 - jl)));
                    float w2 = slcti(0.f, p2, (int)(rb << (23 - jl)));
                    float w3 = slcti(0.f, p3, (int)(rb << (22 - jl)));
                    Alo[h] = packbf(w1, w0);
                    Ahi[h] = packbf(w3, w2);
                }
                #pragma unroll
                for (int n = 0; n < 8; ++n) {
                    const __nv_bfloat16* bp = bbase + (n*8 + lp) * 72 + jk + 2*la;
                    uint32_t b0 = *(const uint32_t*)bp;
                    uint32_t b1 = *(const uint32_t*)(bp + 8);
                    mma16(cA[0][n], Alo[0], Alo[1], Ahi[0], Ahi[1], b0, b1);
                    mma16(cA[1][n], Alo[2], Alo[3], Ahi[2], Ahi[3], b0, b1);
                }
                mma16(cD[0], Alo[0], Alo[1], Ahi[0], Ahi[1], ONES2, ONES2);
                mma16(cD[1], Alo[2], Alo[3], Ahi[2], Ahi[3], ONES2, ONES2);
            }
            __syncthreads();
            buf ^= 1;
        }
        int p = g * ksplit + ks;
        if (la == 0) {
            int r = ibase + w*32 + lp;
            den[(size_t)p * Nn + r]      = cD[0][0];
            den[(size_t)p * Nn + r + 8]  = cD[0][2];
            den[(size_t)p * Nn + r + 16] = cD[1][0];
            den[(size_t)p * Nn + r + 24] = cD[1][2];
        }
        #pragma unroll
        for (int m = 0; m < 2; ++m) {
            int r0 = ibase + w*32 + 16*m + lp;
            #pragma unroll
            for (int n = 0; n < 8; ++n) {
                float* d0 = &part[((size_t)p * Nn + r0) * 64 + n*8 + 2*la];
                *(float2*)d0 = make_float2(cA[m][n][0], cA[m][n][1]);
                *(float2*)(d0 + 8 * 64) = make_float2(cA[m][n][2], cA[m][n][3]);
            }
        }
    }
}

extern "C" void kernel_launch(void* const* d_in, const int* in_sizes, int n_in,
                              void* d_out, int out_size)
{
    const float* x        = (const float*)d_in[0];
    const int*   adj      = (const int*)d_in[1];
    const float* w_heads  = (const float*)d_in[2];
    const float* a_heads  = (const float*)d_in[3];
    const float* w_out    = (const float*)d_in[4];
    const float* a_out    = (const float*)d_in[5];
    const float* lin_w    = (const float*)d_in[6];
    const float* lin_b    = (const float*)d_in[7];
    const float* outlin_w = (const float*)d_in[8];
    const float* outlin_b = (const float*)d_in[9];
    float* out = (float*)d_out;

    float *pXres, *pPart, *pDen;
    __nv_bfloat16 *pWhB, *pWh2B;
    float4 *pRow, *pCol;
    cudaGetSymbolAddress((void**)&pWhB,  g_WhB);
    cudaGetSymbolAddress((void**)&pWh2B, g_Wh2B);
    cudaGetSymbolAddress((void**)&pXres, g_xres);
    cudaGetSymbolAddress((void**)&pPart, g_part);
    cudaGetSymbolAddress((void**)&pDen,  g_den);
    cudaGetSymbolAddress((void**)&pRow,  g_rowdat);
    cudaGetSymbolAddress((void**)&pCol,  g_coldat);

    pack_adj<<<(Nn * Nn) / 256, 256>>>(adj);
    // layer-1: Wh per head -> bf16 transposed + fused scores
    gemm64<<<dim3(Nn/64, 4), 256>>>(x, nullptr, nullptr, 0, w_heads, nullptr, nullptr, 128, 0, 0,
                                    pWhB, a_heads, pRow, pCol, 128L*64, 64L*Nn, 128);
    gemm64<<<dim3(Nn/64, 1), 256>>>(x, nullptr, nullptr, 0, lin_w, lin_b, pXres, 128, 1, 0,
                                    nullptr, nullptr, nullptr, nullptr, 0, 0, 0);
    gat_attn_mma<<<592, 128>>>(pWhB, pRow, pCol, pPart, pDen, 4, 4, 0);
    // layer-2 Wh GEMM with fused combine(part,den) as input, + bf16T + scores
    gemm64<<<dim3(Nn/64, 1), 256>>>(nullptr, pPart, pDen, 4, w_out, nullptr, nullptr, 256, 0, 0,
                                    pWh2B, a_out, pRow, pCol, 0, 0, 0);
    gat_attn_mma<<<592, 128>>>(pWh2B, pRow, pCol, pPart, pDen, 1, 16, 1);
    // final: elu((xres + elu(combine)) @ outlin^T + b)
    gemm64<<<dim3(Nn/64, 1), 256>>>(pXres, pPart, pDen, 16, outlin_w, outlin_b, out, 64, 1, 1,
                                    nullptr, nullptr, nullptr, nullptr, 0, 0, 0);
}